// round 2
// baseline (speedup 1.0000x reference)
#include <cuda_runtime.h>
#include <cuda_bf16.h>
#include <cstdint>

// ---------------- Problem constants ----------------
#define BATCH   2
#define LSEQ    2048
#define NTOK    (BATCH * LSEQ)      // 4096 tokens
#define DMODEL  1024
#define DINNER  2048
#define DSTATE  16
#define DCONV   4
#define DTRANK  64
#define NDBL    (DTRANK + 2 * DSTATE)   // 96

// ---------------- Scratch (device globals; no allocation allowed) ----------
// layout (floats):
//  h     : NTOK*DMODEL            =  4,194,304
//  xz    : NTOK*2*DINNER          = 16,777,216
//  xc    : NTOK*DINNER            =  8,388,608
//  xdbl  : NTOK*NDBL              =    393,216
//  dt    : NTOK*DINNER            =  8,388,608
//  y     : NTOK*DINNER            =  8,388,608
#define OFF_H     ((size_t)0)
#define OFF_XZ    (OFF_H    + (size_t)NTOK * DMODEL)
#define OFF_XC    (OFF_XZ   + (size_t)NTOK * 2 * DINNER)
#define OFF_XDBL  (OFF_XC   + (size_t)NTOK * DINNER)
#define OFF_DT    (OFF_XDBL + (size_t)NTOK * NDBL)
#define OFF_Y     (OFF_DT   + (size_t)NTOK * DINNER)
#define SCRATCH_FLOATS (OFF_Y + (size_t)NTOK * DINNER)

__device__ float g_scratch[SCRATCH_FLOATS];

// ---------------- helpers ----------------
__device__ __forceinline__ float siluf(float z) {
    return z * (1.0f / (1.0f + __expf(-z)));
}
__device__ __forceinline__ float softplusf(float v) {
    return fmaxf(v, 0.0f) + log1pf(expf(-fabsf(v)));
}

// ---------------- 1) add + rmsnorm ----------------
__global__ __launch_bounds__(256) void addnorm_kernel(
    const float* __restrict__ hs,
    const float* __restrict__ res,
    const float* __restrict__ w,
    float* __restrict__ out)
{
    int row = blockIdx.x;               // 0..NTOK-1
    int tid = threadIdx.x;              // 256 threads, 1 float4 each (1024 cols)
    const float4* a4 = (const float4*)(hs  + (size_t)row * DMODEL);
    const float4* b4 = (const float4*)(res + (size_t)row * DMODEL);
    const float4* w4 = (const float4*)w;
    float4 v = a4[tid];
    float4 b = b4[tid];
    v.x += b.x; v.y += b.y; v.z += b.z; v.w += b.w;
    float ss = v.x*v.x + v.y*v.y + v.z*v.z + v.w*v.w;

    // block reduce (8 warps)
    __shared__ float red[8];
    #pragma unroll
    for (int off = 16; off > 0; off >>= 1)
        ss += __shfl_xor_sync(0xffffffffu, ss, off);
    if ((tid & 31) == 0) red[tid >> 5] = ss;
    __syncthreads();
    if (tid < 32) {
        float s = (tid < 8) ? red[tid] : 0.0f;
        #pragma unroll
        for (int off = 4; off > 0; off >>= 1)
            s += __shfl_xor_sync(0xffffffffu, s, off);
        if (tid == 0) red[0] = s;
    }
    __syncthreads();
    float rstd = rsqrtf(red[0] * (1.0f / DMODEL) + 1e-5f);

    float4 ww = w4[tid];
    float4 o;
    o.x = v.x * rstd * ww.x;
    o.y = v.y * rstd * ww.y;
    o.z = v.z * rstd * ww.z;
    o.w = v.w * rstd * ww.w;
    ((float4*)(out + (size_t)row * DMODEL))[tid] = o;
}

// ---------------- 2) generic NT SGEMM:  C[m,n] = sum_k A[m,k] * W[n,k] ------
// BM=BN=128, BK=16, 256 threads, 8x8 per thread. M must be multiple of 128.
// EPI: 0 = plain store, 1 = softplus(c + bias[n])
template <int EPI>
__global__ __launch_bounds__(256) void sgemm_nt(
    const float* __restrict__ A, int lda,
    const float* __restrict__ W,        // [N][K], ld = K
    const float* __restrict__ bias,
    float* __restrict__ C, int ldc,
    int N, int K)
{
    __shared__ float As[16][128];
    __shared__ float Ws[16][128];

    const int tid = threadIdx.x;
    const int m0 = blockIdx.y * 128;
    const int n0 = blockIdx.x * 128;
    const int tx = tid & 15;            // 0..15 (n direction)
    const int ty = tid >> 4;            // 0..15 (m direction)
    const int lr = tid >> 2;            // 0..63 load row
    const int lk = (tid & 3) * 4;       // 0,4,8,12 load k

    float acc[8][8];
    #pragma unroll
    for (int i = 0; i < 8; i++)
        #pragma unroll
        for (int j = 0; j < 8; j++) acc[i][j] = 0.0f;

    for (int k0 = 0; k0 < K; k0 += 16) {
        #pragma unroll
        for (int rr = 0; rr < 2; rr++) {
            int row = lr + rr * 64;
            float4 a = *(const float4*)&A[(size_t)(m0 + row) * lda + k0 + lk];
            As[lk + 0][row] = a.x;
            As[lk + 1][row] = a.y;
            As[lk + 2][row] = a.z;
            As[lk + 3][row] = a.w;
            int n = n0 + row;
            float4 w;
            if (n < N) w = *(const float4*)&W[(size_t)n * K + k0 + lk];
            else       w = make_float4(0.f, 0.f, 0.f, 0.f);
            Ws[lk + 0][row] = w.x;
            Ws[lk + 1][row] = w.y;
            Ws[lk + 2][row] = w.z;
            Ws[lk + 3][row] = w.w;
        }
        __syncthreads();

        #pragma unroll
        for (int kk = 0; kk < 16; kk++) {
            float a[8], b[8];
            float4 a0 = *(const float4*)&As[kk][ty * 8];
            float4 a1 = *(const float4*)&As[kk][ty * 8 + 4];
            float4 b0 = *(const float4*)&Ws[kk][tx * 8];
            float4 b1 = *(const float4*)&Ws[kk][tx * 8 + 4];
            a[0]=a0.x; a[1]=a0.y; a[2]=a0.z; a[3]=a0.w;
            a[4]=a1.x; a[5]=a1.y; a[6]=a1.z; a[7]=a1.w;
            b[0]=b0.x; b[1]=b0.y; b[2]=b0.z; b[3]=b0.w;
            b[4]=b1.x; b[5]=b1.y; b[6]=b1.z; b[7]=b1.w;
            #pragma unroll
            for (int i = 0; i < 8; i++)
                #pragma unroll
                for (int j = 0; j < 8; j++)
                    acc[i][j] = fmaf(a[i], b[j], acc[i][j]);
        }
        __syncthreads();
    }

    // epilogue
    #pragma unroll
    for (int i = 0; i < 8; i++) {
        int m = m0 + ty * 8 + i;
        #pragma unroll
        for (int jj = 0; jj < 2; jj++) {
            int n = n0 + tx * 8 + jj * 4;
            float4 o;
            float* po = &o.x;
            #pragma unroll
            for (int q = 0; q < 4; q++) {
                float v = acc[i][jj * 4 + q];
                if (EPI == 1) v = softplusf(v + bias[n + q < N ? n + q : 0]);
                po[q] = v;
            }
            if (n + 3 < N) {
                *(float4*)&C[(size_t)m * ldc + n] = o;
            } else {
                #pragma unroll
                for (int q = 0; q < 4; q++)
                    if (n + q < N) C[(size_t)m * ldc + n + q] = po[q];
            }
        }
    }
}

// ---------------- 3) causal depthwise conv (k=4) + bias + SiLU -------------
__global__ __launch_bounds__(256) void conv_silu_kernel(
    const float* __restrict__ xz,       // [NTOK][2*DINNER], x part = cols [0,DINNER)
    const float* __restrict__ cw,       // [DINNER][4]
    const float* __restrict__ cb,       // [DINNER]
    float* __restrict__ xc)             // [NTOK][DINNER]
{
    int idx = blockIdx.x * blockDim.x + threadIdx.x;   // over NTOK*DINNER/4
    int dq = idx & (DINNER / 4 - 1);
    int t  = idx / (DINNER / 4);
    int d  = dq * 4;
    int l  = t & (LSEQ - 1);

    float4 bias4 = *(const float4*)&cb[d];
    float acc0 = bias4.x, acc1 = bias4.y, acc2 = bias4.z, acc3 = bias4.w;

    float4 w0 = *(const float4*)&cw[(d + 0) * 4];
    float4 w1 = *(const float4*)&cw[(d + 1) * 4];
    float4 w2 = *(const float4*)&cw[(d + 2) * 4];
    float4 w3 = *(const float4*)&cw[(d + 3) * 4];
    float wv0[4] = {w0.x, w0.y, w0.z, w0.w};
    float wv1[4] = {w1.x, w1.y, w1.z, w1.w};
    float wv2[4] = {w2.x, w2.y, w2.z, w2.w};
    float wv3[4] = {w3.x, w3.y, w3.z, w3.w};

    #pragma unroll
    for (int j = 0; j < 4; j++) {
        int lsrc = l - 3 + j;
        if (lsrc >= 0) {
            float4 v = *(const float4*)&xz[(size_t)(t - 3 + j) * (2 * DINNER) + d];
            acc0 = fmaf(v.x, wv0[j], acc0);
            acc1 = fmaf(v.y, wv1[j], acc1);
            acc2 = fmaf(v.z, wv2[j], acc2);
            acc3 = fmaf(v.w, wv3[j], acc3);
        }
    }
    float4 o;
    o.x = siluf(acc0); o.y = siluf(acc1); o.z = siluf(acc2); o.w = siluf(acc3);
    *(float4*)&xc[(size_t)t * DINNER + d] = o;
}

// ---------------- 4) selective scan ----------------
// Block: 256 threads = 16 channels x 16 states. Grid: BATCH * (DINNER/16) = 256.
__global__ __launch_bounds__(256) void scan_kernel(
    const float* __restrict__ dt,       // [NTOK][DINNER] (softplus applied)
    const float* __restrict__ xz,       // [NTOK][2*DINNER] (z = cols [DINNER,2*DINNER))
    const float* __restrict__ xc,       // [NTOK][DINNER] (conv+silu output)
    const float* __restrict__ xdbl,     // [NTOK][96]; B = cols 64..79, C = 80..95
    const float* __restrict__ A_log,    // [DINNER][16]
    const float* __restrict__ Dp,       // [DINNER]
    float* __restrict__ y)              // [NTOK][DINNER]
{
    const int CH = 64;
    __shared__ float sdt[CH][16], sx[CH][16], sz[CH][16];
    __shared__ float sB[CH][16], sC[CH][16], sy[CH][16];

    int b  = blockIdx.x >> 7;                 // / (DINNER/16)
    int d0 = (blockIdx.x & 127) * 16;
    int tid = threadIdx.x;
    int c = tid >> 4;       // channel in group
    int n = tid & 15;       // state index
    int d = d0 + c;

    float Acoef = -expf(A_log[d * DSTATE + n]);
    float h = 0.0f;

    int e  = tid * 4;
    int le = e >> 4;        // 0..63
    int ie = e & 15;        // 0,4,8,12

    for (int l0 = 0; l0 < LSEQ; l0 += CH) {
        {
            size_t t = (size_t)b * LSEQ + l0 + le;
            *(float4*)&sdt[le][ie] = *(const float4*)&dt[t * DINNER + d0 + ie];
            *(float4*)&sx [le][ie] = *(const float4*)&xc[t * DINNER + d0 + ie];
            *(float4*)&sz [le][ie] = *(const float4*)&xz[t * (2 * DINNER) + DINNER + d0 + ie];
            *(float4*)&sB [le][ie] = *(const float4*)&xdbl[t * NDBL + DTRANK + ie];
            *(float4*)&sC [le][ie] = *(const float4*)&xdbl[t * NDBL + DTRANK + DSTATE + ie];
        }
        __syncthreads();

        #pragma unroll 4
        for (int ll = 0; ll < CH; ll++) {
            float dtv = sdt[ll][c];
            float xv  = sx[ll][c];
            float ea  = __expf(dtv * Acoef);
            h = fmaf(ea, h, dtv * xv * sB[ll][n]);
            float p = h * sC[ll][n];
            p += __shfl_xor_sync(0xffffffffu, p, 8);
            p += __shfl_xor_sync(0xffffffffu, p, 4);
            p += __shfl_xor_sync(0xffffffffu, p, 2);
            p += __shfl_xor_sync(0xffffffffu, p, 1);
            if (n == 0) sy[ll][c] = p;
        }
        __syncthreads();

        {
            size_t t = (size_t)b * LSEQ + l0 + le;
            float4 ys = *(float4*)&sy[le][ie];
            float4 xs = *(float4*)&sx[le][ie];
            float4 zs = *(float4*)&sz[le][ie];
            float4 dd = *(const float4*)&Dp[d0 + ie];
            float4 o;
            o.x = (ys.x + xs.x * dd.x) * siluf(zs.x);
            o.y = (ys.y + xs.y * dd.y) * siluf(zs.y);
            o.z = (ys.z + xs.z * dd.z) * siluf(zs.z);
            o.w = (ys.w + xs.w * dd.w) * siluf(zs.w);
            *(float4*)&y[t * DINNER + d0 + ie] = o;
        }
        __syncthreads();
    }
}

// ---------------- launcher ----------------
extern "C" void kernel_launch(void* const* d_in, const int* in_sizes, int n_in,
                              void* d_out, int out_size)
{
    (void)in_sizes; (void)n_in; (void)out_size;
    // input order per metadata: 0 input_ids(i64, unused), 1 hidden_states,
    // 2 residual, 3 norm_w, 4 in_proj_w, 5 conv_w, 6 conv_b, 7 x_proj_w,
    // 8 dt_proj_w, 9 dt_proj_b, 10 A_log, 11 D_param, 12 out_proj_w
    const float* hs        = (const float*)d_in[1];
    const float* residual  = (const float*)d_in[2];
    const float* norm_w    = (const float*)d_in[3];
    const float* in_proj_w = (const float*)d_in[4];
    const float* conv_w    = (const float*)d_in[5];
    const float* conv_b    = (const float*)d_in[6];
    const float* x_proj_w  = (const float*)d_in[7];
    const float* dt_proj_w = (const float*)d_in[8];
    const float* dt_proj_b = (const float*)d_in[9];
    const float* A_log     = (const float*)d_in[10];
    const float* D_param   = (const float*)d_in[11];
    const float* out_proj_w= (const float*)d_in[12];
    float* out = (float*)d_out;

    static float* scratch = nullptr;
    if (!scratch) {
        void* p = nullptr;
        cudaGetSymbolAddress(&p, g_scratch);
        scratch = (float*)p;
    }
    float* g_h    = scratch + OFF_H;
    float* g_xz   = scratch + OFF_XZ;
    float* g_xc   = scratch + OFF_XC;
    float* g_xdbl = scratch + OFF_XDBL;
    float* g_dt   = scratch + OFF_DT;
    float* g_y    = scratch + OFF_Y;

    // 1) h = rmsnorm(hidden + residual) * w
    addnorm_kernel<<<NTOK, 256>>>(hs, residual, norm_w, g_h);

    // 2) xz = h @ in_proj_w^T      [4096 x 4096], K=1024
    sgemm_nt<0><<<dim3(4096 / 128, NTOK / 128), 256>>>(
        g_h, DMODEL, in_proj_w, nullptr, g_xz, 2 * DINNER, 2 * DINNER, DMODEL);

    // 3) xc = silu(causal_conv(x) + b)
    conv_silu_kernel<<<(NTOK * DINNER / 4) / 256, 256>>>(g_xz, conv_w, conv_b, g_xc);

    // 4) x_dbl = xc @ x_proj_w^T   [4096 x 96], K=2048
    sgemm_nt<0><<<dim3(1, NTOK / 128), 256>>>(
        g_xc, DINNER, x_proj_w, nullptr, g_xdbl, NDBL, NDBL, DINNER);

    // 5) dt = softplus(x_dbl[:, :64] @ dt_proj_w^T + b)   [4096 x 2048], K=64
    sgemm_nt<1><<<dim3(DINNER / 128, NTOK / 128), 256>>>(
        g_xdbl, NDBL, dt_proj_w, dt_proj_b, g_dt, DINNER, DINNER, DTRANK);

    // 6) selective scan + gate -> y
    scan_kernel<<<BATCH * (DINNER / 16), 256>>>(
        g_dt, g_xz, g_xc, g_xdbl, A_log, D_param, g_y);

    // 7) out = y @ out_proj_w^T    [4096 x 1024], K=2048
    sgemm_nt<0><<<dim3(DMODEL / 128, NTOK / 128), 256>>>(
        g_y, DINNER, out_proj_w, nullptr, out, DMODEL, DMODEL, DINNER);
}

// round 4
// speedup vs baseline: 2.0370x; 2.0370x over previous
#include <cuda_runtime.h>
#include <cuda_bf16.h>
#include <cstdint>

// ---------------- Problem constants ----------------
#define BATCH   2
#define LSEQ    2048
#define NTOK    (BATCH * LSEQ)      // 4096 tokens
#define DMODEL  1024
#define DINNER  2048
#define DSTATE  16
#define DCONV   4
#define DTRANK  64
#define NDBL    (DTRANK + 2 * DSTATE)   // 96

// ---------------- Scratch (device globals; no allocation allowed) ----------
#define OFF_H     ((size_t)0)
#define OFF_XZ    (OFF_H    + (size_t)NTOK * DMODEL)
#define OFF_XC    (OFF_XZ   + (size_t)NTOK * 2 * DINNER)
#define OFF_XDBL  (OFF_XC   + (size_t)NTOK * DINNER)
#define OFF_DT    (OFF_XDBL + (size_t)NTOK * NDBL)
#define OFF_Y     (OFF_DT   + (size_t)NTOK * DINNER)
#define SCRATCH_FLOATS (OFF_Y + (size_t)NTOK * DINNER)

__device__ float g_scratch[SCRATCH_FLOATS];

// ---------------- helpers ----------------
__device__ __forceinline__ float siluf(float z) {
    return z * (1.0f / (1.0f + __expf(-z)));
}
__device__ __forceinline__ float softplusf(float v) {
    return fmaxf(v, 0.0f) + log1pf(expf(-fabsf(v)));
}

__device__ __forceinline__ uint32_t smem_u32(const void* p) {
    uint32_t addr;
    asm("{ .reg .u64 tmp; cvta.to.shared.u64 tmp, %1; cvt.u32.u64 %0, tmp; }"
        : "=r"(addr) : "l"(p));
    return addr;
}

__device__ __forceinline__ void cp16(uint32_t dst, const void* src) {
    asm volatile("cp.async.cg.shared.global [%0], [%1], 16;" :: "r"(dst), "l"(src));
}
__device__ __forceinline__ void cp_commit() {
    asm volatile("cp.async.commit_group;");
}
template <int N>
__device__ __forceinline__ void cp_wait() {
    asm volatile("cp.async.wait_group %0;" :: "n"(N));
}

__device__ __forceinline__ uint32_t to_tf32(float v) {
    uint32_t u;
    asm("cvt.rna.tf32.f32 %0, %1;" : "=r"(u) : "f"(v));
    return u;
}

__device__ __forceinline__ void mma_tf32(
    float& c0, float& c1, float& c2, float& c3,
    uint32_t a0, uint32_t a1, uint32_t a2, uint32_t a3,
    uint32_t b0, uint32_t b1)
{
    asm volatile(
        "mma.sync.aligned.m16n8k8.row.col.f32.tf32.tf32.f32 "
        "{%0,%1,%2,%3}, {%4,%5,%6,%7}, {%8,%9}, {%0,%1,%2,%3};"
        : "+f"(c0), "+f"(c1), "+f"(c2), "+f"(c3)
        : "r"(a0), "r"(a1), "r"(a2), "r"(a3), "r"(b0), "r"(b1));
}

// ---------------- TF32 tensor-core GEMM: C[m,n] = sum_k A[m,k] * W[n,k] ----
// CTA: 128x128x32, 256 threads, 8 warps (2 along M x 4 along N), warp 64x32.
// Double-buffered cp.async. EPI: 0 = plain, 1 = softplus(c + bias[n]).
#define SM_STRIDE 36                       // floats per smem row (128+pad)
#define TILE_FLOATS (128 * SM_STRIDE)      // 4608
#define BUF_BYTES  (TILE_FLOATS * 4)       // 18432
#define MM_SMEM_BYTES (4 * BUF_BYTES)      // 73728

__device__ __forceinline__ void stage_tile(
    uint32_t sA, uint32_t sB,
    const float* __restrict__ A, int lda,
    const float* __restrict__ W, int K, int Nw,
    int m0, int n0, int k0, int tid)
{
    #pragma unroll
    for (int i = 0; i < 4; i++) {
        int idx = i * 256 + tid;            // 0..1023
        int row = idx >> 3;
        int kc  = idx & 7;                  // 16B chunk (4 floats)
        cp16(sA + (uint32_t)(row * SM_STRIDE + kc * 4) * 4,
             &A[(size_t)(m0 + row) * lda + k0 + kc * 4]);
    }
    #pragma unroll
    for (int i = 0; i < 4; i++) {
        int idx = i * 256 + tid;
        int row = idx >> 3;
        int kc  = idx & 7;
        int n = n0 + row;
        int nn = (n < Nw) ? n : 0;          // clamp; garbage cols never stored
        cp16(sB + (uint32_t)(row * SM_STRIDE + kc * 4) * 4,
             &W[(size_t)nn * K + k0 + kc * 4]);
    }
}

template <int EPI>
__global__ __launch_bounds__(256) void mm_tf32(
    const float* __restrict__ A, int lda,
    const float* __restrict__ W, int Nw,     // valid W rows
    const float* __restrict__ bias,
    float* __restrict__ C, int ldc, int Nc,  // valid C cols
    int K)
{
    extern __shared__ float smem_f[];
    const uint32_t sbase = smem_u32(smem_f);
    const int tid  = threadIdx.x;
    const int wid  = tid >> 5;
    const int lane = tid & 31;
    const int g    = lane >> 2;              // 0..7
    const int t4   = lane & 3;               // 0..3
    const int wm   = wid >> 2;               // 0..1
    const int wn   = wid & 3;                // 0..3
    const int mW   = wm * 64;
    const int nW   = wn * 32;
    const int m0 = blockIdx.y * 128;
    const int n0 = blockIdx.x * 128;
    const int iters = K / 32;

    const uint32_t sA[2] = {sbase,                sbase + 2 * BUF_BYTES};
    const uint32_t sB[2] = {sbase + BUF_BYTES,    sbase + 3 * BUF_BYTES};
    const float* fA[2] = {smem_f,                   smem_f + 2 * TILE_FLOATS};
    const float* fB[2] = {smem_f + TILE_FLOATS,     smem_f + 3 * TILE_FLOATS};

    float acc[4][4][4];
    #pragma unroll
    for (int i = 0; i < 4; i++)
        #pragma unroll
        for (int j = 0; j < 4; j++)
            #pragma unroll
            for (int q = 0; q < 4; q++) acc[i][j][q] = 0.0f;

    // prologue: stage tiles 0 and 1
    stage_tile(sA[0], sB[0], A, lda, W, K, Nw, m0, n0, 0, tid);
    cp_commit();
    stage_tile(sA[1], sB[1], A, lda, W, K, Nw, m0, n0, 32, tid);
    cp_commit();

    for (int it = 0; it < iters; it++) {
        const int p = it & 1;
        if (it + 1 < iters) cp_wait<1>(); else cp_wait<0>();
        __syncthreads();

        const float* As = fA[p];
        const float* Bs = fB[p];
        #pragma unroll
        for (int ks = 0; ks < 4; ks++) {
            const int k = ks * 8 + t4;
            uint32_t af[4][4];
            uint32_t bf[4][2];
            #pragma unroll
            for (int i = 0; i < 4; i++) {
                int r0 = mW + i * 16 + g;
                af[i][0] = to_tf32(As[r0 * SM_STRIDE + k]);
                af[i][1] = to_tf32(As[(r0 + 8) * SM_STRIDE + k]);
                af[i][2] = to_tf32(As[r0 * SM_STRIDE + k + 4]);
                af[i][3] = to_tf32(As[(r0 + 8) * SM_STRIDE + k + 4]);
            }
            #pragma unroll
            for (int j = 0; j < 4; j++) {
                int n = nW + j * 8 + g;
                bf[j][0] = to_tf32(Bs[n * SM_STRIDE + k]);
                bf[j][1] = to_tf32(Bs[n * SM_STRIDE + k + 4]);
            }
            #pragma unroll
            for (int i = 0; i < 4; i++)
                #pragma unroll
                for (int j = 0; j < 4; j++)
                    mma_tf32(acc[i][j][0], acc[i][j][1], acc[i][j][2], acc[i][j][3],
                             af[i][0], af[i][1], af[i][2], af[i][3],
                             bf[j][0], bf[j][1]);
        }
        __syncthreads();

        if (it + 2 < iters) {
            stage_tile(sA[p], sB[p], A, lda, W, K, Nw, m0, n0, (it + 2) * 32, tid);
            cp_commit();
        }
    }

    // ---- epilogue: registers -> global (float2 stores, 32B coalesced) ----
    #pragma unroll
    for (int i = 0; i < 4; i++) {
        #pragma unroll
        for (int j = 0; j < 4; j++) {
            int col = n0 + nW + j * 8 + t4 * 2;
            if (col < Nc) {
                int row0 = m0 + mW + i * 16 + g;
                float2 v0 = make_float2(acc[i][j][0], acc[i][j][1]);
                float2 v1 = make_float2(acc[i][j][2], acc[i][j][3]);
                if (EPI == 1) {
                    v0.x = softplusf(v0.x + bias[col]);
                    v0.y = softplusf(v0.y + bias[col + 1]);
                    v1.x = softplusf(v1.x + bias[col]);
                    v1.y = softplusf(v1.y + bias[col + 1]);
                }
                *(float2*)&C[(size_t)row0 * ldc + col]       = v0;
                *(float2*)&C[(size_t)(row0 + 8) * ldc + col] = v1;
            }
        }
    }
}

// ---------------- 1) add + rmsnorm ----------------
__global__ __launch_bounds__(256) void addnorm_kernel(
    const float* __restrict__ hs,
    const float* __restrict__ res,
    const float* __restrict__ w,
    float* __restrict__ out)
{
    int row = blockIdx.x;
    int tid = threadIdx.x;
    const float4* a4 = (const float4*)(hs  + (size_t)row * DMODEL);
    const float4* b4 = (const float4*)(res + (size_t)row * DMODEL);
    const float4* w4 = (const float4*)w;
    float4 v = a4[tid];
    float4 b = b4[tid];
    v.x += b.x; v.y += b.y; v.z += b.z; v.w += b.w;
    float ss = v.x*v.x + v.y*v.y + v.z*v.z + v.w*v.w;

    __shared__ float red[8];
    #pragma unroll
    for (int off = 16; off > 0; off >>= 1)
        ss += __shfl_xor_sync(0xffffffffu, ss, off);
    if ((tid & 31) == 0) red[tid >> 5] = ss;
    __syncthreads();
    if (tid < 32) {
        float s = (tid < 8) ? red[tid] : 0.0f;
        #pragma unroll
        for (int off = 4; off > 0; off >>= 1)
            s += __shfl_xor_sync(0xffffffffu, s, off);
        if (tid == 0) red[0] = s;
    }
    __syncthreads();
    float rstd = rsqrtf(red[0] * (1.0f / DMODEL) + 1e-5f);

    float4 ww = w4[tid];
    float4 o;
    o.x = v.x * rstd * ww.x;
    o.y = v.y * rstd * ww.y;
    o.z = v.z * rstd * ww.z;
    o.w = v.w * rstd * ww.w;
    ((float4*)(out + (size_t)row * DMODEL))[tid] = o;
}

// ---------------- 3) causal depthwise conv (k=4) + bias + SiLU -------------
__global__ __launch_bounds__(256) void conv_silu_kernel(
    const float* __restrict__ xz,
    const float* __restrict__ cw,
    const float* __restrict__ cb,
    float* __restrict__ xc)
{
    int idx = blockIdx.x * blockDim.x + threadIdx.x;
    int dq = idx & (DINNER / 4 - 1);
    int t  = idx / (DINNER / 4);
    int d  = dq * 4;
    int l  = t & (LSEQ - 1);

    float4 bias4 = *(const float4*)&cb[d];
    float acc0 = bias4.x, acc1 = bias4.y, acc2 = bias4.z, acc3 = bias4.w;

    float4 w0 = *(const float4*)&cw[(d + 0) * 4];
    float4 w1 = *(const float4*)&cw[(d + 1) * 4];
    float4 w2 = *(const float4*)&cw[(d + 2) * 4];
    float4 w3 = *(const float4*)&cw[(d + 3) * 4];
    float wv0[4] = {w0.x, w0.y, w0.z, w0.w};
    float wv1[4] = {w1.x, w1.y, w1.z, w1.w};
    float wv2[4] = {w2.x, w2.y, w2.z, w2.w};
    float wv3[4] = {w3.x, w3.y, w3.z, w3.w};

    #pragma unroll
    for (int j = 0; j < 4; j++) {
        int lsrc = l - 3 + j;
        if (lsrc >= 0) {
            float4 v = *(const float4*)&xz[(size_t)(t - 3 + j) * (2 * DINNER) + d];
            acc0 = fmaf(v.x, wv0[j], acc0);
            acc1 = fmaf(v.y, wv1[j], acc1);
            acc2 = fmaf(v.z, wv2[j], acc2);
            acc3 = fmaf(v.w, wv3[j], acc3);
        }
    }
    float4 o;
    o.x = siluf(acc0); o.y = siluf(acc1); o.z = siluf(acc2); o.w = siluf(acc3);
    *(float4*)&xc[(size_t)t * DINNER + d] = o;
}

// ---------------- 4) selective scan ----------------
__global__ __launch_bounds__(256) void scan_kernel(
    const float* __restrict__ dt,
    const float* __restrict__ xz,
    const float* __restrict__ xc,
    const float* __restrict__ xdbl,
    const float* __restrict__ A_log,
    const float* __restrict__ Dp,
    float* __restrict__ y)
{
    const int CH = 64;
    __shared__ float sdt[CH][16], sx[CH][16], sz[CH][16];
    __shared__ float sB[CH][16], sC[CH][16], sy[CH][16];

    int b  = blockIdx.x >> 7;
    int d0 = (blockIdx.x & 127) * 16;
    int tid = threadIdx.x;
    int c = tid >> 4;
    int n = tid & 15;
    int d = d0 + c;

    float Acoef = -expf(A_log[d * DSTATE + n]);
    float h = 0.0f;

    int e  = tid * 4;
    int le = e >> 4;
    int ie = e & 15;

    for (int l0 = 0; l0 < LSEQ; l0 += CH) {
        {
            size_t t = (size_t)b * LSEQ + l0 + le;
            *(float4*)&sdt[le][ie] = *(const float4*)&dt[t * DINNER + d0 + ie];
            *(float4*)&sx [le][ie] = *(const float4*)&xc[t * DINNER + d0 + ie];
            *(float4*)&sz [le][ie] = *(const float4*)&xz[t * (2 * DINNER) + DINNER + d0 + ie];
            *(float4*)&sB [le][ie] = *(const float4*)&xdbl[t * NDBL + DTRANK + ie];
            *(float4*)&sC [le][ie] = *(const float4*)&xdbl[t * NDBL + DTRANK + DSTATE + ie];
        }
        __syncthreads();

        #pragma unroll 4
        for (int ll = 0; ll < CH; ll++) {
            float dtv = sdt[ll][c];
            float xv  = sx[ll][c];
            float ea  = __expf(dtv * Acoef);
            h = fmaf(ea, h, dtv * xv * sB[ll][n]);
            float p = h * sC[ll][n];
            p += __shfl_xor_sync(0xffffffffu, p, 8);
            p += __shfl_xor_sync(0xffffffffu, p, 4);
            p += __shfl_xor_sync(0xffffffffu, p, 2);
            p += __shfl_xor_sync(0xffffffffu, p, 1);
            if (n == 0) sy[ll][c] = p;
        }
        __syncthreads();

        {
            size_t t = (size_t)b * LSEQ + l0 + le;
            float4 ys = *(float4*)&sy[le][ie];
            float4 xs = *(float4*)&sx[le][ie];
            float4 zs = *(float4*)&sz[le][ie];
            float4 dd = *(const float4*)&Dp[d0 + ie];
            float4 o;
            o.x = (ys.x + xs.x * dd.x) * siluf(zs.x);
            o.y = (ys.y + xs.y * dd.y) * siluf(zs.y);
            o.z = (ys.z + xs.z * dd.z) * siluf(zs.z);
            o.w = (ys.w + xs.w * dd.w) * siluf(zs.w);
            *(float4*)&y[t * DINNER + d0 + ie] = o;
        }
        __syncthreads();
    }
}

// ---------------- launcher ----------------
extern "C" void kernel_launch(void* const* d_in, const int* in_sizes, int n_in,
                              void* d_out, int out_size)
{
    (void)in_sizes; (void)n_in; (void)out_size;
    const float* hs        = (const float*)d_in[1];
    const float* residual  = (const float*)d_in[2];
    const float* norm_w    = (const float*)d_in[3];
    const float* in_proj_w = (const float*)d_in[4];
    const float* conv_w    = (const float*)d_in[5];
    const float* conv_b    = (const float*)d_in[6];
    const float* x_proj_w  = (const float*)d_in[7];
    const float* dt_proj_w = (const float*)d_in[8];
    const float* dt_proj_b = (const float*)d_in[9];
    const float* A_log     = (const float*)d_in[10];
    const float* D_param   = (const float*)d_in[11];
    const float* out_proj_w= (const float*)d_in[12];
    float* out = (float*)d_out;

    static float* scratch = nullptr;
    if (!scratch) {
        void* p = nullptr;
        cudaGetSymbolAddress(&p, g_scratch);
        scratch = (float*)p;
        cudaFuncSetAttribute(mm_tf32<0>, cudaFuncAttributeMaxDynamicSharedMemorySize, MM_SMEM_BYTES);
        cudaFuncSetAttribute(mm_tf32<1>, cudaFuncAttributeMaxDynamicSharedMemorySize, MM_SMEM_BYTES);
    }
    float* g_h    = scratch + OFF_H;
    float* g_xz   = scratch + OFF_XZ;
    float* g_xc   = scratch + OFF_XC;
    float* g_xdbl = scratch + OFF_XDBL;
    float* g_dt   = scratch + OFF_DT;
    float* g_y    = scratch + OFF_Y;

    // 1) h = rmsnorm(hidden + residual) * w
    addnorm_kernel<<<NTOK, 256>>>(hs, residual, norm_w, g_h);

    // 2) xz = h @ in_proj_w^T   [4096 x 4096], K=1024
    mm_tf32<0><<<dim3(4096 / 128, NTOK / 128), 256, MM_SMEM_BYTES>>>(
        g_h, DMODEL, in_proj_w, 2 * DINNER, nullptr,
        g_xz, 2 * DINNER, 2 * DINNER, DMODEL);

    // 3) xc = silu(causal_conv(x) + b)
    conv_silu_kernel<<<(NTOK * DINNER / 4) / 256, 256>>>(g_xz, conv_w, conv_b, g_xc);

    // 4) x_dbl = xc @ x_proj_w^T   [4096 x 96], K=2048
    mm_tf32<0><<<dim3(1, NTOK / 128), 256, MM_SMEM_BYTES>>>(
        g_xc, DINNER, x_proj_w, NDBL, nullptr,
        g_xdbl, NDBL, NDBL, DINNER);

    // 5) dt = softplus(x_dbl[:, :64] @ dt_proj_w^T + b)   [4096 x 2048], K=64
    mm_tf32<1><<<dim3(DINNER / 128, NTOK / 128), 256, MM_SMEM_BYTES>>>(
        g_xdbl, NDBL, dt_proj_w, DINNER, dt_proj_b,
        g_dt, DINNER, DINNER, DTRANK);

    // 6) selective scan + gate -> y
    scan_kernel<<<BATCH * (DINNER / 16), 256>>>(
        g_dt, g_xz, g_xc, g_xdbl, A_log, D_param, g_y);

    // 7) out = y @ out_proj_w^T   [4096 x 1024], K=2048
    mm_tf32<0><<<dim3(DMODEL / 128, NTOK / 128), 256, MM_SMEM_BYTES>>>(
        g_y, DINNER, out_proj_w, DMODEL, nullptr,
        out, DMODEL, DMODEL, DINNER);
}

// round 5
// speedup vs baseline: 2.3126x; 1.1353x over previous
#include <cuda_runtime.h>
#include <cuda_bf16.h>
#include <cstdint>

// ---------------- Problem constants ----------------
#define BATCH   2
#define LSEQ    2048
#define NTOK    (BATCH * LSEQ)      // 4096 tokens
#define DMODEL  1024
#define DINNER  2048
#define DSTATE  16
#define DCONV   4
#define DTRANK  64
#define NDBL    (DTRANK + 2 * DSTATE)   // 96
#define XP_SPLITS 8

// ---------------- Scratch (device globals; no allocation allowed) ----------
#define OFF_H     ((size_t)0)
#define OFF_XZ    (OFF_H    + (size_t)NTOK * DMODEL)
#define OFF_XC    (OFF_XZ   + (size_t)NTOK * 2 * DINNER)
#define OFF_XDBL  (OFF_XC   + (size_t)NTOK * DINNER)
#define OFF_DT    (OFF_XDBL + (size_t)NTOK * NDBL)
#define OFF_Y     (OFF_DT   + (size_t)NTOK * DINNER)
#define OFF_XP    (OFF_Y    + (size_t)NTOK * DINNER)
#define SCRATCH_FLOATS (OFF_XP + (size_t)XP_SPLITS * NTOK * NDBL)

__device__ float g_scratch[SCRATCH_FLOATS];

// ---------------- helpers ----------------
__device__ __forceinline__ float siluf(float z) {
    return z * (1.0f / (1.0f + __expf(-z)));
}
__device__ __forceinline__ float softplusf(float v) {
    return fmaxf(v, 0.0f) + log1pf(expf(-fabsf(v)));
}

__device__ __forceinline__ uint32_t smem_u32(const void* p) {
    uint32_t addr;
    asm("{ .reg .u64 tmp; cvta.to.shared.u64 tmp, %1; cvt.u32.u64 %0, tmp; }"
        : "=r"(addr) : "l"(p));
    return addr;
}

__device__ __forceinline__ void cp16(uint32_t dst, const void* src) {
    asm volatile("cp.async.cg.shared.global [%0], [%1], 16;" :: "r"(dst), "l"(src));
}
__device__ __forceinline__ void cp_commit() {
    asm volatile("cp.async.commit_group;");
}
template <int N>
__device__ __forceinline__ void cp_wait() {
    asm volatile("cp.async.wait_group %0;" :: "n"(N));
}

__device__ __forceinline__ uint32_t to_tf32(float v) {
    uint32_t u;
    asm("cvt.rna.tf32.f32 %0, %1;" : "=r"(u) : "f"(v));
    return u;
}

__device__ __forceinline__ void mma_tf32(
    float& c0, float& c1, float& c2, float& c3,
    uint32_t a0, uint32_t a1, uint32_t a2, uint32_t a3,
    uint32_t b0, uint32_t b1)
{
    asm volatile(
        "mma.sync.aligned.m16n8k8.row.col.f32.tf32.tf32.f32 "
        "{%0,%1,%2,%3}, {%4,%5,%6,%7}, {%8,%9}, {%0,%1,%2,%3};"
        : "+f"(c0), "+f"(c1), "+f"(c2), "+f"(c3)
        : "r"(a0), "r"(a1), "r"(a2), "r"(a3), "r"(b0), "r"(b1));
}

// ---------------- TF32 tensor-core GEMM: C[m,n] = sum_k A[m,k] * W[n,k] ----
// CTA: 128x128x32, 256 threads, 8 warps (2 along M x 4 along N), warp 64x32.
// Double-buffered cp.async. EPI: 0 = plain, 1 = softplus(c + bias[n]).
// Split-K via gridDim.z: each z-slice handles K contiguous k's starting at
// blockIdx.z*K and writes to C + blockIdx.z*cSlice.
#define SM_STRIDE 36                       // floats per smem row (128+pad)
#define TILE_FLOATS (128 * SM_STRIDE)      // 4608
#define BUF_BYTES  (TILE_FLOATS * 4)       // 18432
#define MM_SMEM_BYTES (4 * BUF_BYTES)      // 73728

__device__ __forceinline__ void stage_tile(
    uint32_t sA, uint32_t sB,
    const float* __restrict__ A, int lda,
    const float* __restrict__ W, int ldw, int Nw,
    int m0, int n0, int k0, int tid)
{
    #pragma unroll
    for (int i = 0; i < 4; i++) {
        int idx = i * 256 + tid;            // 0..1023
        int row = idx >> 3;
        int kc  = idx & 7;                  // 16B chunk (4 floats)
        cp16(sA + (uint32_t)(row * SM_STRIDE + kc * 4) * 4,
             &A[(size_t)(m0 + row) * lda + k0 + kc * 4]);
    }
    #pragma unroll
    for (int i = 0; i < 4; i++) {
        int idx = i * 256 + tid;
        int row = idx >> 3;
        int kc  = idx & 7;
        int n = n0 + row;
        int nn = (n < Nw) ? n : 0;          // clamp; garbage cols never stored
        cp16(sB + (uint32_t)(row * SM_STRIDE + kc * 4) * 4,
             &W[(size_t)nn * ldw + k0 + kc * 4]);
    }
}

template <int EPI>
__global__ __launch_bounds__(256, 2) void mm_tf32(
    const float* __restrict__ A, int lda,
    const float* __restrict__ W, int Nw,     // valid W rows
    const float* __restrict__ bias,
    float* __restrict__ C, int ldc, int Nc,  // valid C cols
    int K,                                    // K per z-slice
    size_t cSlice)                            // C offset per z-slice
{
    extern __shared__ float smem_f[];
    const uint32_t sbase = smem_u32(smem_f);
    const int tid  = threadIdx.x;
    const int wid  = tid >> 5;
    const int lane = tid & 31;
    const int g    = lane >> 2;              // 0..7
    const int t4   = lane & 3;               // 0..3
    const int wm   = wid >> 2;               // 0..1
    const int wn   = wid & 3;                // 0..3
    const int mW   = wm * 64;
    const int nW   = wn * 32;
    const int m0 = blockIdx.y * 128;
    const int n0 = blockIdx.x * 128;
    const int kBase = blockIdx.z * K;
    const int iters = K / 32;

    C += (size_t)blockIdx.z * cSlice;

    const uint32_t sA[2] = {sbase,                sbase + 2 * BUF_BYTES};
    const uint32_t sB[2] = {sbase + BUF_BYTES,    sbase + 3 * BUF_BYTES};
    const float* fA[2] = {smem_f,                   smem_f + 2 * TILE_FLOATS};
    const float* fB[2] = {smem_f + TILE_FLOATS,     smem_f + 3 * TILE_FLOATS};

    float acc[4][4][4];
    #pragma unroll
    for (int i = 0; i < 4; i++)
        #pragma unroll
        for (int j = 0; j < 4; j++)
            #pragma unroll
            for (int q = 0; q < 4; q++) acc[i][j][q] = 0.0f;

    const int ldw = K * gridDim.z;          // full weight row length

    // prologue: stage tiles 0 and 1
    stage_tile(sA[0], sB[0], A, lda, W, ldw, Nw, m0, n0, kBase, tid);
    cp_commit();
    stage_tile(sA[1], sB[1], A, lda, W, ldw, Nw, m0, n0, kBase + 32, tid);
    cp_commit();

    for (int it = 0; it < iters; it++) {
        const int p = it & 1;
        if (it + 1 < iters) cp_wait<1>(); else cp_wait<0>();
        __syncthreads();

        const float* As = fA[p];
        const float* Bs = fB[p];
        #pragma unroll
        for (int ks = 0; ks < 4; ks++) {
            const int k = ks * 8 + t4;
            uint32_t af[4][4];
            uint32_t bf[4][2];
            #pragma unroll
            for (int i = 0; i < 4; i++) {
                int r0 = mW + i * 16 + g;
                af[i][0] = to_tf32(As[r0 * SM_STRIDE + k]);
                af[i][1] = to_tf32(As[(r0 + 8) * SM_STRIDE + k]);
                af[i][2] = to_tf32(As[r0 * SM_STRIDE + k + 4]);
                af[i][3] = to_tf32(As[(r0 + 8) * SM_STRIDE + k + 4]);
            }
            #pragma unroll
            for (int j = 0; j < 4; j++) {
                int n = nW + j * 8 + g;
                bf[j][0] = to_tf32(Bs[n * SM_STRIDE + k]);
                bf[j][1] = to_tf32(Bs[n * SM_STRIDE + k + 4]);
            }
            #pragma unroll
            for (int i = 0; i < 4; i++)
                #pragma unroll
                for (int j = 0; j < 4; j++)
                    mma_tf32(acc[i][j][0], acc[i][j][1], acc[i][j][2], acc[i][j][3],
                             af[i][0], af[i][1], af[i][2], af[i][3],
                             bf[j][0], bf[j][1]);
        }
        __syncthreads();

        if (it + 2 < iters) {
            stage_tile(sA[p], sB[p], A, lda, W, ldw, Nw, m0, n0,
                       kBase + (it + 2) * 32, tid);
            cp_commit();
        }
    }

    // ---- epilogue: registers -> global (float2 stores, 32B coalesced) ----
    #pragma unroll
    for (int i = 0; i < 4; i++) {
        #pragma unroll
        for (int j = 0; j < 4; j++) {
            int col = n0 + nW + j * 8 + t4 * 2;
            if (col < Nc) {
                int row0 = m0 + mW + i * 16 + g;
                float2 v0 = make_float2(acc[i][j][0], acc[i][j][1]);
                float2 v1 = make_float2(acc[i][j][2], acc[i][j][3]);
                if (EPI == 1) {
                    v0.x = softplusf(v0.x + bias[col]);
                    v0.y = softplusf(v0.y + bias[col + 1]);
                    v1.x = softplusf(v1.x + bias[col]);
                    v1.y = softplusf(v1.y + bias[col + 1]);
                }
                *(float2*)&C[(size_t)row0 * ldc + col]       = v0;
                *(float2*)&C[(size_t)(row0 + 8) * ldc + col] = v1;
            }
        }
    }
}

// ---------------- split-K partial reduce: out = sum_s part[s] ----------------
__global__ __launch_bounds__(256) void reduce_splits_kernel(
    const float* __restrict__ part, float* __restrict__ out, int n4)
{
    int i = blockIdx.x * blockDim.x + threadIdx.x;
    if (i >= n4) return;
    const float4* p = (const float4*)part;
    float4 s = p[i];
    #pragma unroll
    for (int k = 1; k < XP_SPLITS; k++) {
        float4 v = p[(size_t)k * n4 + i];
        s.x += v.x; s.y += v.y; s.z += v.z; s.w += v.w;
    }
    ((float4*)out)[i] = s;
}

// ---------------- 1) add + rmsnorm ----------------
__global__ __launch_bounds__(256) void addnorm_kernel(
    const float* __restrict__ hs,
    const float* __restrict__ res,
    const float* __restrict__ w,
    float* __restrict__ out)
{
    int row = blockIdx.x;
    int tid = threadIdx.x;
    const float4* a4 = (const float4*)(hs  + (size_t)row * DMODEL);
    const float4* b4 = (const float4*)(res + (size_t)row * DMODEL);
    const float4* w4 = (const float4*)w;
    float4 v = a4[tid];
    float4 b = b4[tid];
    v.x += b.x; v.y += b.y; v.z += b.z; v.w += b.w;
    float ss = v.x*v.x + v.y*v.y + v.z*v.z + v.w*v.w;

    __shared__ float red[8];
    #pragma unroll
    for (int off = 16; off > 0; off >>= 1)
        ss += __shfl_xor_sync(0xffffffffu, ss, off);
    if ((tid & 31) == 0) red[tid >> 5] = ss;
    __syncthreads();
    if (tid < 32) {
        float s = (tid < 8) ? red[tid] : 0.0f;
        #pragma unroll
        for (int off = 4; off > 0; off >>= 1)
            s += __shfl_xor_sync(0xffffffffu, s, off);
        if (tid == 0) red[0] = s;
    }
    __syncthreads();
    float rstd = rsqrtf(red[0] * (1.0f / DMODEL) + 1e-5f);

    float4 ww = w4[tid];
    float4 o;
    o.x = v.x * rstd * ww.x;
    o.y = v.y * rstd * ww.y;
    o.z = v.z * rstd * ww.z;
    o.w = v.w * rstd * ww.w;
    ((float4*)(out + (size_t)row * DMODEL))[tid] = o;
}

// ---------------- 3) causal depthwise conv (k=4) + bias + SiLU -------------
__global__ __launch_bounds__(256) void conv_silu_kernel(
    const float* __restrict__ xz,
    const float* __restrict__ cw,
    const float* __restrict__ cb,
    float* __restrict__ xc)
{
    int idx = blockIdx.x * blockDim.x + threadIdx.x;
    int dq = idx & (DINNER / 4 - 1);
    int t  = idx / (DINNER / 4);
    int d  = dq * 4;
    int l  = t & (LSEQ - 1);

    float4 bias4 = *(const float4*)&cb[d];
    float acc0 = bias4.x, acc1 = bias4.y, acc2 = bias4.z, acc3 = bias4.w;

    float4 w0 = *(const float4*)&cw[(d + 0) * 4];
    float4 w1 = *(const float4*)&cw[(d + 1) * 4];
    float4 w2 = *(const float4*)&cw[(d + 2) * 4];
    float4 w3 = *(const float4*)&cw[(d + 3) * 4];
    float wv0[4] = {w0.x, w0.y, w0.z, w0.w};
    float wv1[4] = {w1.x, w1.y, w1.z, w1.w};
    float wv2[4] = {w2.x, w2.y, w2.z, w2.w};
    float wv3[4] = {w3.x, w3.y, w3.z, w3.w};

    #pragma unroll
    for (int j = 0; j < 4; j++) {
        int lsrc = l - 3 + j;
        if (lsrc >= 0) {
            float4 v = *(const float4*)&xz[(size_t)(t - 3 + j) * (2 * DINNER) + d];
            acc0 = fmaf(v.x, wv0[j], acc0);
            acc1 = fmaf(v.y, wv1[j], acc1);
            acc2 = fmaf(v.z, wv2[j], acc2);
            acc3 = fmaf(v.w, wv3[j], acc3);
        }
    }
    float4 o;
    o.x = siluf(acc0); o.y = siluf(acc1); o.z = siluf(acc2); o.w = siluf(acc3);
    *(float4*)&xc[(size_t)t * DINNER + d] = o;
}

// ---------------- 4) selective scan ----------------
__global__ __launch_bounds__(256) void scan_kernel(
    const float* __restrict__ dt,
    const float* __restrict__ xz,
    const float* __restrict__ xc,
    const float* __restrict__ xdbl,
    const float* __restrict__ A_log,
    const float* __restrict__ Dp,
    float* __restrict__ y)
{
    const int CH = 64;
    __shared__ float sdt[CH][16], sx[CH][16], sz[CH][16];
    __shared__ float sB[CH][16], sC[CH][16], sy[CH][16];

    int b  = blockIdx.x >> 7;
    int d0 = (blockIdx.x & 127) * 16;
    int tid = threadIdx.x;
    int c = tid >> 4;
    int n = tid & 15;
    int d = d0 + c;

    float Acoef = -expf(A_log[d * DSTATE + n]);
    float h = 0.0f;

    int e  = tid * 4;
    int le = e >> 4;
    int ie = e & 15;

    for (int l0 = 0; l0 < LSEQ; l0 += CH) {
        {
            size_t t = (size_t)b * LSEQ + l0 + le;
            *(float4*)&sdt[le][ie] = *(const float4*)&dt[t * DINNER + d0 + ie];
            *(float4*)&sx [le][ie] = *(const float4*)&xc[t * DINNER + d0 + ie];
            *(float4*)&sz [le][ie] = *(const float4*)&xz[t * (2 * DINNER) + DINNER + d0 + ie];
            *(float4*)&sB [le][ie] = *(const float4*)&xdbl[t * NDBL + DTRANK + ie];
            *(float4*)&sC [le][ie] = *(const float4*)&xdbl[t * NDBL + DTRANK + DSTATE + ie];
        }
        __syncthreads();

        #pragma unroll 4
        for (int ll = 0; ll < CH; ll++) {
            float dtv = sdt[ll][c];
            float xv  = sx[ll][c];
            float ea  = __expf(dtv * Acoef);
            h = fmaf(ea, h, dtv * xv * sB[ll][n]);
            float p = h * sC[ll][n];
            p += __shfl_xor_sync(0xffffffffu, p, 8);
            p += __shfl_xor_sync(0xffffffffu, p, 4);
            p += __shfl_xor_sync(0xffffffffu, p, 2);
            p += __shfl_xor_sync(0xffffffffu, p, 1);
            if (n == 0) sy[ll][c] = p;
        }
        __syncthreads();

        {
            size_t t = (size_t)b * LSEQ + l0 + le;
            float4 ys = *(float4*)&sy[le][ie];
            float4 xs = *(float4*)&sx[le][ie];
            float4 zs = *(float4*)&sz[le][ie];
            float4 dd = *(const float4*)&Dp[d0 + ie];
            float4 o;
            o.x = (ys.x + xs.x * dd.x) * siluf(zs.x);
            o.y = (ys.y + xs.y * dd.y) * siluf(zs.y);
            o.z = (ys.z + xs.z * dd.z) * siluf(zs.z);
            o.w = (ys.w + xs.w * dd.w) * siluf(zs.w);
            *(float4*)&y[t * DINNER + d0 + ie] = o;
        }
        __syncthreads();
    }
}

// ---------------- launcher ----------------
extern "C" void kernel_launch(void* const* d_in, const int* in_sizes, int n_in,
                              void* d_out, int out_size)
{
    (void)in_sizes; (void)n_in; (void)out_size;
    const float* hs        = (const float*)d_in[1];
    const float* residual  = (const float*)d_in[2];
    const float* norm_w    = (const float*)d_in[3];
    const float* in_proj_w = (const float*)d_in[4];
    const float* conv_w    = (const float*)d_in[5];
    const float* conv_b    = (const float*)d_in[6];
    const float* x_proj_w  = (const float*)d_in[7];
    const float* dt_proj_w = (const float*)d_in[8];
    const float* dt_proj_b = (const float*)d_in[9];
    const float* A_log     = (const float*)d_in[10];
    const float* D_param   = (const float*)d_in[11];
    const float* out_proj_w= (const float*)d_in[12];
    float* out = (float*)d_out;

    static float* scratch = nullptr;
    if (!scratch) {
        void* p = nullptr;
        cudaGetSymbolAddress(&p, g_scratch);
        scratch = (float*)p;
        cudaFuncSetAttribute(mm_tf32<0>, cudaFuncAttributeMaxDynamicSharedMemorySize, MM_SMEM_BYTES);
        cudaFuncSetAttribute(mm_tf32<1>, cudaFuncAttributeMaxDynamicSharedMemorySize, MM_SMEM_BYTES);
    }
    float* g_h    = scratch + OFF_H;
    float* g_xz   = scratch + OFF_XZ;
    float* g_xc   = scratch + OFF_XC;
    float* g_xdbl = scratch + OFF_XDBL;
    float* g_dt   = scratch + OFF_DT;
    float* g_y    = scratch + OFF_Y;
    float* g_xp   = scratch + OFF_XP;

    // 1) h = rmsnorm(hidden + residual) * w
    addnorm_kernel<<<NTOK, 256>>>(hs, residual, norm_w, g_h);

    // 2) xz = h @ in_proj_w^T   [4096 x 4096], K=1024
    mm_tf32<0><<<dim3(4096 / 128, NTOK / 128, 1), 256, MM_SMEM_BYTES>>>(
        g_h, DMODEL, in_proj_w, 2 * DINNER, nullptr,
        g_xz, 2 * DINNER, 2 * DINNER, DMODEL, 0);

    // 3) xc = silu(causal_conv(x) + b)
    conv_silu_kernel<<<(NTOK * DINNER / 4) / 256, 256>>>(g_xz, conv_w, conv_b, g_xc);

    // 4) x_dbl partials = xc @ x_proj_w^T   [4096 x 96], K=2048, split-K=8
    mm_tf32<0><<<dim3(1, NTOK / 128, XP_SPLITS), 256, MM_SMEM_BYTES>>>(
        g_xc, DINNER, x_proj_w, NDBL, nullptr,
        g_xp, NDBL, NDBL, DINNER / XP_SPLITS, (size_t)NTOK * NDBL);
    reduce_splits_kernel<<<(NTOK * NDBL / 4 + 255) / 256, 256>>>(
        g_xp, g_xdbl, NTOK * NDBL / 4);

    // 5) dt = softplus(x_dbl[:, :64] @ dt_proj_w^T + b)   [4096 x 2048], K=64
    mm_tf32<1><<<dim3(DINNER / 128, NTOK / 128, 1), 256, MM_SMEM_BYTES>>>(
        g_xdbl, NDBL, dt_proj_w, DINNER, dt_proj_b,
        g_dt, DINNER, DINNER, DTRANK, 0);

    // 6) selective scan + gate -> y
    scan_kernel<<<BATCH * (DINNER / 16), 256>>>(
        g_dt, g_xz, g_xc, g_xdbl, A_log, D_param, g_y);

    // 7) out = y @ out_proj_w^T   [4096 x 1024], K=2048
    mm_tf32<0><<<dim3(DMODEL / 128, NTOK / 128, 1), 256, MM_SMEM_BYTES>>>(
        g_y, DINNER, out_proj_w, DMODEL, nullptr,
        out, DMODEL, DMODEL, DINNER, 0);
}

// round 6
// speedup vs baseline: 2.5899x; 1.1199x over previous
#include <cuda_runtime.h>
#include <cuda_bf16.h>
#include <cstdint>

// ---------------- Problem constants ----------------
#define BATCH   2
#define LSEQ    2048
#define NTOK    (BATCH * LSEQ)      // 4096 tokens
#define DMODEL  1024
#define DINNER  2048
#define DSTATE  16
#define DCONV   4
#define DTRANK  64
#define NDBL    (DTRANK + 2 * DSTATE)   // 96
#define XP_SPLITS 8

// weight sizes (floats)
#define W_IN_SZ   ((size_t)2 * DINNER * DMODEL)   // 4,194,304
#define W_XP_SZ   ((size_t)NDBL * DINNER)         //   196,608
#define W_DT_SZ   ((size_t)DINNER * DTRANK)       //   131,072
#define W_OP_SZ   ((size_t)DMODEL * DINNER)       // 2,097,152

// ---------------- Scratch (device globals; no allocation allowed) ----------
#define OFF_H     ((size_t)0)
#define OFF_XZ    (OFF_H    + (size_t)NTOK * DMODEL)
#define OFF_XC    (OFF_XZ   + (size_t)NTOK * 2 * DINNER)
#define OFF_XDBL  (OFF_XC   + (size_t)NTOK * DINNER)
#define OFF_DT    (OFF_XDBL + (size_t)NTOK * NDBL)
#define OFF_Y     (OFF_DT   + (size_t)NTOK * DINNER)
#define OFF_XP    (OFF_Y    + (size_t)NTOK * DINNER)
#define OFF_WIN   (OFF_XP   + (size_t)XP_SPLITS * NTOK * NDBL)
#define OFF_WXP   (OFF_WIN  + W_IN_SZ)
#define OFF_WDT   (OFF_WXP  + W_XP_SZ)
#define OFF_WOP   (OFF_WDT  + W_DT_SZ)
#define SCRATCH_FLOATS (OFF_WOP + W_OP_SZ)

__device__ float g_scratch[SCRATCH_FLOATS];

// ---------------- helpers ----------------
__device__ __forceinline__ float siluf(float z) {
    return z * (1.0f / (1.0f + __expf(-z)));
}
__device__ __forceinline__ float softplusf(float v) {
    return fmaxf(v, 0.0f) + log1pf(expf(-fabsf(v)));
}

__device__ __forceinline__ uint32_t smem_u32(const void* p) {
    uint32_t addr;
    asm("{ .reg .u64 tmp; cvta.to.shared.u64 tmp, %1; cvt.u32.u64 %0, tmp; }"
        : "=r"(addr) : "l"(p));
    return addr;
}

__device__ __forceinline__ void cp16(uint32_t dst, const void* src) {
    asm volatile("cp.async.cg.shared.global [%0], [%1], 16;" :: "r"(dst), "l"(src));
}
__device__ __forceinline__ void cp_commit() {
    asm volatile("cp.async.commit_group;");
}
template <int N>
__device__ __forceinline__ void cp_wait() {
    asm volatile("cp.async.wait_group %0;" :: "n"(N));
}

__device__ __forceinline__ uint32_t to_tf32(float v) {
    uint32_t u;
    asm("cvt.rna.tf32.f32 %0, %1;" : "=r"(u) : "f"(v));
    return u;
}
__device__ __forceinline__ float round_tf32(float v) {
    return __uint_as_float(to_tf32(v));
}

__device__ __forceinline__ void mma_tf32(
    float& c0, float& c1, float& c2, float& c3,
    uint32_t a0, uint32_t a1, uint32_t a2, uint32_t a3,
    uint32_t b0, uint32_t b1)
{
    asm volatile(
        "mma.sync.aligned.m16n8k8.row.col.f32.tf32.tf32.f32 "
        "{%0,%1,%2,%3}, {%4,%5,%6,%7}, {%8,%9}, {%0,%1,%2,%3};"
        : "+f"(c0), "+f"(c1), "+f"(c2), "+f"(c3)
        : "r"(a0), "r"(a1), "r"(a2), "r"(a3), "r"(b0), "r"(b1));
}

// ---------------- weight pre-rounding: out = cvt.rna.tf32(in) --------------
__global__ __launch_bounds__(256) void round_copy_kernel(
    const float4* __restrict__ in, float4* __restrict__ out, int n4)
{
    int i = blockIdx.x * blockDim.x + threadIdx.x;
    if (i >= n4) return;
    float4 v = in[i];
    v.x = round_tf32(v.x); v.y = round_tf32(v.y);
    v.z = round_tf32(v.z); v.w = round_tf32(v.w);
    out[i] = v;
}

// ---------------- TF32 tensor-core GEMM: C[m,n] = sum_k A[m,k] * W[n,k] ----
// CTA: 128x128x32, 256 threads, 8 warps (2 M x 4 N), warp 64x32.
// 3-stage cp.async pipeline, ONE __syncthreads per k-iter.
// EPI: 0 = plain, 1 = softplus(c + bias[n]).
// CVTA: true => cvt A operands in-loop (A not pre-rounded). B always pre-rounded.
// Split-K via gridDim.z.
#define SM_STRIDE 36                       // floats per smem row (128+pad)
#define TILE_FLOATS (128 * SM_STRIDE)      // 4608
#define BUF_BYTES  (TILE_FLOATS * 4)       // 18432
#define MM_SMEM_BYTES (6 * BUF_BYTES)      // 110592 (3 stages x (A+B))

__device__ __forceinline__ void stage_tile(
    uint32_t sA, uint32_t sB,
    const float* __restrict__ A, int lda,
    const float* __restrict__ W, int ldw, int Nw,
    int m0, int n0, int k0, int tid)
{
    #pragma unroll
    for (int i = 0; i < 4; i++) {
        int idx = i * 256 + tid;            // 0..1023
        int row = idx >> 3;
        int kc  = idx & 7;                  // 16B chunk (4 floats)
        cp16(sA + (uint32_t)(row * SM_STRIDE + kc * 4) * 4,
             &A[(size_t)(m0 + row) * lda + k0 + kc * 4]);
    }
    #pragma unroll
    for (int i = 0; i < 4; i++) {
        int idx = i * 256 + tid;
        int row = idx >> 3;
        int kc  = idx & 7;
        int n = n0 + row;
        int nn = (n < Nw) ? n : 0;          // clamp; garbage cols never stored
        cp16(sB + (uint32_t)(row * SM_STRIDE + kc * 4) * 4,
             &W[(size_t)nn * ldw + k0 + kc * 4]);
    }
}

template <int EPI, bool CVTA>
__global__ __launch_bounds__(256, 2) void mm_tf32(
    const float* __restrict__ A, int lda,
    const float* __restrict__ W, int Nw,     // valid W rows
    const float* __restrict__ bias,
    float* __restrict__ C, int ldc, int Nc,  // valid C cols
    int K,                                    // K per z-slice
    size_t cSlice)                            // C offset per z-slice
{
    extern __shared__ float smem_f[];
    const uint32_t sbase = smem_u32(smem_f);
    const int tid  = threadIdx.x;
    const int wid  = tid >> 5;
    const int lane = tid & 31;
    const int g    = lane >> 2;              // 0..7
    const int t4   = lane & 3;               // 0..3
    const int wm   = wid >> 2;               // 0..1
    const int wn   = wid & 3;                // 0..3
    const int mW   = wm * 64;
    const int nW   = wn * 32;
    const int m0 = blockIdx.y * 128;
    const int n0 = blockIdx.x * 128;
    const int kBase = blockIdx.z * K;
    const int iters = K / 32;

    C += (size_t)blockIdx.z * cSlice;
    const int ldw = K * gridDim.z;          // full weight row length

    float acc[4][4][4];
    #pragma unroll
    for (int i = 0; i < 4; i++)
        #pragma unroll
        for (int j = 0; j < 4; j++)
            #pragma unroll
            for (int q = 0; q < 4; q++) acc[i][j][q] = 0.0f;

    // prologue: stage tiles 0 and 1 into buffers 0 and 1
    stage_tile(sbase, sbase + BUF_BYTES, A, lda, W, ldw, Nw, m0, n0, kBase, tid);
    cp_commit();
    stage_tile(sbase + 2 * BUF_BYTES, sbase + 3 * BUF_BYTES,
               A, lda, W, ldw, Nw, m0, n0, kBase + 32, tid);
    cp_commit();

    for (int it = 0; it < iters; it++) {
        cp_wait<1>();                        // tile 'it' complete (my groups)
        __syncthreads();                     // visible to all; prev compute done

        // stage tile it+2 into buffer (it+2)%3 (freed by compute of it-1)
        if (it + 2 < iters) {
            int s = (it + 2) % 3;
            stage_tile(sbase + (uint32_t)(2 * s) * BUF_BYTES,
                       sbase + (uint32_t)(2 * s + 1) * BUF_BYTES,
                       A, lda, W, ldw, Nw, m0, n0, kBase + (it + 2) * 32, tid);
        }
        cp_commit();                         // commit (possibly empty) group

        const int p = it % 3;
        const float* As = smem_f + (size_t)(2 * p) * TILE_FLOATS;
        const float* Bs = smem_f + (size_t)(2 * p + 1) * TILE_FLOATS;

        #pragma unroll
        for (int ks = 0; ks < 4; ks++) {
            const int k = ks * 8 + t4;
            uint32_t af[4][4];
            uint32_t bf[4][2];
            #pragma unroll
            for (int i = 0; i < 4; i++) {
                int r0 = mW + i * 16 + g;
                if (CVTA) {
                    af[i][0] = to_tf32(As[r0 * SM_STRIDE + k]);
                    af[i][1] = to_tf32(As[(r0 + 8) * SM_STRIDE + k]);
                    af[i][2] = to_tf32(As[r0 * SM_STRIDE + k + 4]);
                    af[i][3] = to_tf32(As[(r0 + 8) * SM_STRIDE + k + 4]);
                } else {
                    af[i][0] = __float_as_uint(As[r0 * SM_STRIDE + k]);
                    af[i][1] = __float_as_uint(As[(r0 + 8) * SM_STRIDE + k]);
                    af[i][2] = __float_as_uint(As[r0 * SM_STRIDE + k + 4]);
                    af[i][3] = __float_as_uint(As[(r0 + 8) * SM_STRIDE + k + 4]);
                }
            }
            #pragma unroll
            for (int j = 0; j < 4; j++) {
                int n = nW + j * 8 + g;
                bf[j][0] = __float_as_uint(Bs[n * SM_STRIDE + k]);
                bf[j][1] = __float_as_uint(Bs[n * SM_STRIDE + k + 4]);
            }
            #pragma unroll
            for (int i = 0; i < 4; i++)
                #pragma unroll
                for (int j = 0; j < 4; j++)
                    mma_tf32(acc[i][j][0], acc[i][j][1], acc[i][j][2], acc[i][j][3],
                             af[i][0], af[i][1], af[i][2], af[i][3],
                             bf[j][0], bf[j][1]);
        }
    }

    // ---- epilogue: registers -> global (float2 stores, 32B coalesced) ----
    #pragma unroll
    for (int i = 0; i < 4; i++) {
        #pragma unroll
        for (int j = 0; j < 4; j++) {
            int col = n0 + nW + j * 8 + t4 * 2;
            if (col < Nc) {
                int row0 = m0 + mW + i * 16 + g;
                float2 v0 = make_float2(acc[i][j][0], acc[i][j][1]);
                float2 v1 = make_float2(acc[i][j][2], acc[i][j][3]);
                if (EPI == 1) {
                    v0.x = softplusf(v0.x + bias[col]);
                    v0.y = softplusf(v0.y + bias[col + 1]);
                    v1.x = softplusf(v1.x + bias[col]);
                    v1.y = softplusf(v1.y + bias[col + 1]);
                }
                *(float2*)&C[(size_t)row0 * ldc + col]       = v0;
                *(float2*)&C[(size_t)(row0 + 8) * ldc + col] = v1;
            }
        }
    }
}

// ---------------- split-K partial reduce: out = sum_s part[s] ----------------
// Rounds cols < DTRANK to tf32 (they only feed the dt GEMM); B/C stay fp32.
__global__ __launch_bounds__(256) void reduce_splits_kernel(
    const float* __restrict__ part, float* __restrict__ out, int n4)
{
    int i = blockIdx.x * blockDim.x + threadIdx.x;
    if (i >= n4) return;
    const float4* p = (const float4*)part;
    float4 s = p[i];
    #pragma unroll
    for (int k = 1; k < XP_SPLITS; k++) {
        float4 v = p[(size_t)k * n4 + i];
        s.x += v.x; s.y += v.y; s.z += v.z; s.w += v.w;
    }
    if ((i % (NDBL / 4)) < (DTRANK / 4)) {   // cols 0..63 -> dt GEMM input
        s.x = round_tf32(s.x); s.y = round_tf32(s.y);
        s.z = round_tf32(s.z); s.w = round_tf32(s.w);
    }
    ((float4*)out)[i] = s;
}

// ---------------- 1) add + rmsnorm (output rounded to tf32) ----------------
__global__ __launch_bounds__(256) void addnorm_kernel(
    const float* __restrict__ hs,
    const float* __restrict__ res,
    const float* __restrict__ w,
    float* __restrict__ out)
{
    int row = blockIdx.x;
    int tid = threadIdx.x;
    const float4* a4 = (const float4*)(hs  + (size_t)row * DMODEL);
    const float4* b4 = (const float4*)(res + (size_t)row * DMODEL);
    const float4* w4 = (const float4*)w;
    float4 v = a4[tid];
    float4 b = b4[tid];
    v.x += b.x; v.y += b.y; v.z += b.z; v.w += b.w;
    float ss = v.x*v.x + v.y*v.y + v.z*v.z + v.w*v.w;

    __shared__ float red[8];
    #pragma unroll
    for (int off = 16; off > 0; off >>= 1)
        ss += __shfl_xor_sync(0xffffffffu, ss, off);
    if ((tid & 31) == 0) red[tid >> 5] = ss;
    __syncthreads();
    if (tid < 32) {
        float s = (tid < 8) ? red[tid] : 0.0f;
        #pragma unroll
        for (int off = 4; off > 0; off >>= 1)
            s += __shfl_xor_sync(0xffffffffu, s, off);
        if (tid == 0) red[0] = s;
    }
    __syncthreads();
    float rstd = rsqrtf(red[0] * (1.0f / DMODEL) + 1e-5f);

    float4 ww = w4[tid];
    float4 o;
    o.x = round_tf32(v.x * rstd * ww.x);
    o.y = round_tf32(v.y * rstd * ww.y);
    o.z = round_tf32(v.z * rstd * ww.z);
    o.w = round_tf32(v.w * rstd * ww.w);
    ((float4*)(out + (size_t)row * DMODEL))[tid] = o;
}

// ---------------- 3) causal depthwise conv (k=4) + bias + SiLU -------------
__global__ __launch_bounds__(256) void conv_silu_kernel(
    const float* __restrict__ xz,
    const float* __restrict__ cw,
    const float* __restrict__ cb,
    float* __restrict__ xc)
{
    int idx = blockIdx.x * blockDim.x + threadIdx.x;
    int dq = idx & (DINNER / 4 - 1);
    int t  = idx / (DINNER / 4);
    int d  = dq * 4;
    int l  = t & (LSEQ - 1);

    float4 bias4 = *(const float4*)&cb[d];
    float acc0 = bias4.x, acc1 = bias4.y, acc2 = bias4.z, acc3 = bias4.w;

    float4 w0 = *(const float4*)&cw[(d + 0) * 4];
    float4 w1 = *(const float4*)&cw[(d + 1) * 4];
    float4 w2 = *(const float4*)&cw[(d + 2) * 4];
    float4 w3 = *(const float4*)&cw[(d + 3) * 4];
    float wv0[4] = {w0.x, w0.y, w0.z, w0.w};
    float wv1[4] = {w1.x, w1.y, w1.z, w1.w};
    float wv2[4] = {w2.x, w2.y, w2.z, w2.w};
    float wv3[4] = {w3.x, w3.y, w3.z, w3.w};

    #pragma unroll
    for (int j = 0; j < 4; j++) {
        int lsrc = l - 3 + j;
        if (lsrc >= 0) {
            float4 v = *(const float4*)&xz[(size_t)(t - 3 + j) * (2 * DINNER) + d];
            acc0 = fmaf(v.x, wv0[j], acc0);
            acc1 = fmaf(v.y, wv1[j], acc1);
            acc2 = fmaf(v.z, wv2[j], acc2);
            acc3 = fmaf(v.w, wv3[j], acc3);
        }
    }
    float4 o;
    o.x = siluf(acc0); o.y = siluf(acc1); o.z = siluf(acc2); o.w = siluf(acc3);
    *(float4*)&xc[(size_t)t * DINNER + d] = o;
}

// ---------------- 4) selective scan (y output rounded to tf32) -------------
__global__ __launch_bounds__(256) void scan_kernel(
    const float* __restrict__ dt,
    const float* __restrict__ xz,
    const float* __restrict__ xc,
    const float* __restrict__ xdbl,
    const float* __restrict__ A_log,
    const float* __restrict__ Dp,
    float* __restrict__ y)
{
    const int CH = 64;
    __shared__ float sdt[CH][16], sx[CH][16], sz[CH][16];
    __shared__ float sB[CH][16], sC[CH][16], sy[CH][16];

    int b  = blockIdx.x >> 7;
    int d0 = (blockIdx.x & 127) * 16;
    int tid = threadIdx.x;
    int c = tid >> 4;
    int n = tid & 15;
    int d = d0 + c;

    float Acoef = -expf(A_log[d * DSTATE + n]);
    float h = 0.0f;

    int e  = tid * 4;
    int le = e >> 4;
    int ie = e & 15;

    for (int l0 = 0; l0 < LSEQ; l0 += CH) {
        {
            size_t t = (size_t)b * LSEQ + l0 + le;
            *(float4*)&sdt[le][ie] = *(const float4*)&dt[t * DINNER + d0 + ie];
            *(float4*)&sx [le][ie] = *(const float4*)&xc[t * DINNER + d0 + ie];
            *(float4*)&sz [le][ie] = *(const float4*)&xz[t * (2 * DINNER) + DINNER + d0 + ie];
            *(float4*)&sB [le][ie] = *(const float4*)&xdbl[t * NDBL + DTRANK + ie];
            *(float4*)&sC [le][ie] = *(const float4*)&xdbl[t * NDBL + DTRANK + DSTATE + ie];
        }
        __syncthreads();

        #pragma unroll 4
        for (int ll = 0; ll < CH; ll++) {
            float dtv = sdt[ll][c];
            float xv  = sx[ll][c];
            float ea  = __expf(dtv * Acoef);
            h = fmaf(ea, h, dtv * xv * sB[ll][n]);
            float p = h * sC[ll][n];
            p += __shfl_xor_sync(0xffffffffu, p, 8);
            p += __shfl_xor_sync(0xffffffffu, p, 4);
            p += __shfl_xor_sync(0xffffffffu, p, 2);
            p += __shfl_xor_sync(0xffffffffu, p, 1);
            if (n == 0) sy[ll][c] = p;
        }
        __syncthreads();

        {
            size_t t = (size_t)b * LSEQ + l0 + le;
            float4 ys = *(float4*)&sy[le][ie];
            float4 xs = *(float4*)&sx[le][ie];
            float4 zs = *(float4*)&sz[le][ie];
            float4 dd = *(const float4*)&Dp[d0 + ie];
            float4 o;
            o.x = round_tf32((ys.x + xs.x * dd.x) * siluf(zs.x));
            o.y = round_tf32((ys.y + xs.y * dd.y) * siluf(zs.y));
            o.z = round_tf32((ys.z + xs.z * dd.z) * siluf(zs.z));
            o.w = round_tf32((ys.w + xs.w * dd.w) * siluf(zs.w));
            *(float4*)&y[t * DINNER + d0 + ie] = o;
        }
        __syncthreads();
    }
}

// ---------------- launcher ----------------
extern "C" void kernel_launch(void* const* d_in, const int* in_sizes, int n_in,
                              void* d_out, int out_size)
{
    (void)in_sizes; (void)n_in; (void)out_size;
    const float* hs        = (const float*)d_in[1];
    const float* residual  = (const float*)d_in[2];
    const float* norm_w    = (const float*)d_in[3];
    const float* in_proj_w = (const float*)d_in[4];
    const float* conv_w    = (const float*)d_in[5];
    const float* conv_b    = (const float*)d_in[6];
    const float* x_proj_w  = (const float*)d_in[7];
    const float* dt_proj_w = (const float*)d_in[8];
    const float* dt_proj_b = (const float*)d_in[9];
    const float* A_log     = (const float*)d_in[10];
    const float* D_param   = (const float*)d_in[11];
    const float* out_proj_w= (const float*)d_in[12];
    float* out = (float*)d_out;

    static float* scratch = nullptr;
    if (!scratch) {
        void* p = nullptr;
        cudaGetSymbolAddress(&p, g_scratch);
        scratch = (float*)p;
        cudaFuncSetAttribute(mm_tf32<0, false>, cudaFuncAttributeMaxDynamicSharedMemorySize, MM_SMEM_BYTES);
        cudaFuncSetAttribute(mm_tf32<0, true>,  cudaFuncAttributeMaxDynamicSharedMemorySize, MM_SMEM_BYTES);
        cudaFuncSetAttribute(mm_tf32<1, false>, cudaFuncAttributeMaxDynamicSharedMemorySize, MM_SMEM_BYTES);
    }
    float* g_h    = scratch + OFF_H;
    float* g_xz   = scratch + OFF_XZ;
    float* g_xc   = scratch + OFF_XC;
    float* g_xdbl = scratch + OFF_XDBL;
    float* g_dt   = scratch + OFF_DT;
    float* g_y    = scratch + OFF_Y;
    float* g_xp   = scratch + OFF_XP;
    float* g_win  = scratch + OFF_WIN;
    float* g_wxp  = scratch + OFF_WXP;
    float* g_wdt  = scratch + OFF_WDT;
    float* g_wop  = scratch + OFF_WOP;

    // 0) pre-round weights to tf32 (removes in-loop cvt on B everywhere)
    round_copy_kernel<<<(int)(W_IN_SZ / 4 + 255) / 256, 256>>>(
        (const float4*)in_proj_w, (float4*)g_win, (int)(W_IN_SZ / 4));
    round_copy_kernel<<<(int)(W_XP_SZ / 4 + 255) / 256, 256>>>(
        (const float4*)x_proj_w, (float4*)g_wxp, (int)(W_XP_SZ / 4));
    round_copy_kernel<<<(int)(W_DT_SZ / 4 + 255) / 256, 256>>>(
        (const float4*)dt_proj_w, (float4*)g_wdt, (int)(W_DT_SZ / 4));
    round_copy_kernel<<<(int)(W_OP_SZ / 4 + 255) / 256, 256>>>(
        (const float4*)out_proj_w, (float4*)g_wop, (int)(W_OP_SZ / 4));

    // 1) h = round_tf32(rmsnorm(hidden + residual) * w)
    addnorm_kernel<<<NTOK, 256>>>(hs, residual, norm_w, g_h);

    // 2) xz = h @ in_proj_w^T   [4096 x 4096], K=1024
    mm_tf32<0, false><<<dim3(4096 / 128, NTOK / 128, 1), 256, MM_SMEM_BYTES>>>(
        g_h, DMODEL, g_win, 2 * DINNER, nullptr,
        g_xz, 2 * DINNER, 2 * DINNER, DMODEL, 0);

    // 3) xc = silu(causal_conv(x) + b)   (stays fp32: feeds scan too)
    conv_silu_kernel<<<(NTOK * DINNER / 4) / 256, 256>>>(g_xz, conv_w, conv_b, g_xc);

    // 4) x_dbl partials = xc @ x_proj_w^T   [4096 x 96], K=2048, split-K=8
    mm_tf32<0, true><<<dim3(1, NTOK / 128, XP_SPLITS), 256, MM_SMEM_BYTES>>>(
        g_xc, DINNER, g_wxp, NDBL, nullptr,
        g_xp, NDBL, NDBL, DINNER / XP_SPLITS, (size_t)NTOK * NDBL);
    reduce_splits_kernel<<<(NTOK * NDBL / 4 + 255) / 256, 256>>>(
        g_xp, g_xdbl, NTOK * NDBL / 4);

    // 5) dt = softplus(x_dbl[:, :64] @ dt_proj_w^T + b)   [4096 x 2048], K=64
    mm_tf32<1, false><<<dim3(DINNER / 128, NTOK / 128, 1), 256, MM_SMEM_BYTES>>>(
        g_xdbl, NDBL, g_wdt, DINNER, dt_proj_b,
        g_dt, DINNER, DINNER, DTRANK, 0);

    // 6) selective scan + gate -> y (rounded to tf32 for out_proj)
    scan_kernel<<<BATCH * (DINNER / 16), 256>>>(
        g_dt, g_xz, g_xc, g_xdbl, A_log, D_param, g_y);

    // 7) out = y @ out_proj_w^T   [4096 x 1024], K=2048
    mm_tf32<0, false><<<dim3(DMODEL / 128, NTOK / 128, 1), 256, MM_SMEM_BYTES>>>(
        g_y, DINNER, g_wop, DMODEL, nullptr,
        out, DMODEL, DMODEL, DINNER, 0);
}